// round 1
// baseline (speedup 1.0000x reference)
#include <cuda_runtime.h>
#include <math.h>

// Problem constants
#define BB   64
#define TT   52
#define TDEC 51
#define HD   512
#define EE   512
#define GG   2048        // 4*H
#define VV   32000
#define PRED_ELEMS (BB*TDEC*VV)   // 104,448,000

// ------------------------ device scratch (no allocs allowed) ------------------------
__device__ int   g_sort_ind[BB];
__device__ int   g_declen[BB];          // sorted (descending) decode lengths
__device__ int   g_nt[TDEC];            // #active rows at step t (prefix property)
__device__ int   g_caps[BB*TT];         // sorted captions
__device__ float g_h[BB*HD];
__device__ float g_c[BB*HD];
__device__ float g_gates[BB*GG];        // h @ W_hh^T per step
__device__ float g_X[(size_t)TDEC*BB*GG];     // x @ W_ih^T + b_ih + b_hh  (26.7 MB)
__device__ float g_Hbuf[(size_t)TDEC*BB*HD];  // h_new history (6.7 MB)

// ------------------------ kernel 1: sort + gathers + init ------------------------
__global__ void setup_kernel(const float* __restrict__ img,
                             const int*   __restrict__ caps_in,
                             const int*   __restrict__ lens,
                             float* __restrict__ out, int out_elems)
{
    __shared__ int s_len[BB];
    int tid = threadIdx.x;
    if (tid < BB) s_len[tid] = lens[tid];
    __syncthreads();

    if (tid == 0) {
        // stable descending selection sort == jnp.argsort(-lengths) (stable)
        unsigned long long used = 0ull;
        for (int p = 0; p < BB; ++p) {
            int best = -1, bl = -1000000;
            for (int j = 0; j < BB; ++j) {
                if (!((used >> j) & 1ull) && s_len[j] > bl) { bl = s_len[j]; best = j; }
            }
            used |= 1ull << best;
            g_sort_ind[p] = best;
            g_declen[p]   = bl - 1;
        }
    }
    __syncthreads();

    if (tid < TDEC) {
        int cnt = 0;
        for (int p = 0; p < BB; ++p) cnt += (g_declen[p] > tid) ? 1 : 0;
        g_nt[tid] = cnt;
    }

    bool write_tail = (out_elems >= PRED_ELEMS + BB*TT + 2*BB);

    for (int idx = tid; idx < BB*TT; idx += blockDim.x) {
        int p = idx / TT, j = idx - p*TT;
        int c = caps_in[g_sort_ind[p]*TT + j];
        g_caps[idx] = c;
        if (write_tail) out[PRED_ELEMS + idx] = (float)c;
    }
    for (int idx = tid; idx < BB*HD; idx += blockDim.x) {
        int p = idx >> 9;
        g_h[idx] = img[g_sort_ind[p]*HD + (idx & (HD-1))];
        g_c[idx] = 0.f;
    }
    if (write_tail && tid < BB) {
        out[PRED_ELEMS + BB*TT + tid]      = (float)g_declen[tid];
        out[PRED_ELEMS + BB*TT + BB + tid] = (float)g_sort_ind[tid];
    }
}

// ------------------------ kernel 2: X = emb @ W_ih^T + b_ih + b_hh ------------------------
// grid: (GG/128, TDEC), block 256. Tile 64(b) x 128(g), BK=16. Warp covers 8 rows -> skip inactive.
__global__ void xgate_kernel(const float* __restrict__ embW,
                             const float* __restrict__ Wih,
                             const float* __restrict__ bih,
                             const float* __restrict__ bhh)
{
    int t  = blockIdx.y;
    int n  = g_nt[t];
    if (n == 0) return;
    int j0 = blockIdx.x * 128;

    __shared__ float As[16][65];
    __shared__ float Bs[16][129];

    int tid = threadIdx.x;
    int tx = tid & 15, ty = tid >> 4;
    int row_base = ty * 4;
    bool docomp = (row_base < n);

    int lrow = tid >> 2;           // 0..63
    int lk4  = (tid & 3) * 4;      // 0,4,8,12
    int cap  = g_caps[lrow * TT + t];
    const float* arow = embW + (size_t)cap * EE;

    int ln = tid >> 1;             // 0..127
    int lh = (tid & 1) * 8;        // 0,8
    const float* brow = Wih + (size_t)(j0 + ln) * EE;

    float acc[4][8];
#pragma unroll
    for (int r = 0; r < 4; ++r)
#pragma unroll
        for (int i = 0; i < 8; ++i) acc[r][i] = 0.f;

    for (int k0 = 0; k0 < EE; k0 += 16) {
        float4 av  = *(const float4*)(arow + k0 + lk4);
        float4 bv0 = *(const float4*)(brow + k0 + lh);
        float4 bv1 = *(const float4*)(brow + k0 + lh + 4);
        __syncthreads();
        As[lk4+0][lrow]=av.x; As[lk4+1][lrow]=av.y; As[lk4+2][lrow]=av.z; As[lk4+3][lrow]=av.w;
        Bs[lh+0][ln]=bv0.x; Bs[lh+1][ln]=bv0.y; Bs[lh+2][ln]=bv0.z; Bs[lh+3][ln]=bv0.w;
        Bs[lh+4][ln]=bv1.x; Bs[lh+5][ln]=bv1.y; Bs[lh+6][ln]=bv1.z; Bs[lh+7][ln]=bv1.w;
        __syncthreads();
        if (docomp) {
#pragma unroll
            for (int k = 0; k < 16; ++k) {
                float a0 = As[k][row_base+0], a1 = As[k][row_base+1];
                float a2 = As[k][row_base+2], a3 = As[k][row_base+3];
#pragma unroll
                for (int i = 0; i < 8; ++i) {
                    float bv = Bs[k][tx + 16*i];
                    acc[0][i] += a0*bv; acc[1][i] += a1*bv;
                    acc[2][i] += a2*bv; acc[3][i] += a3*bv;
                }
            }
        }
    }
    if (docomp) {
#pragma unroll
        for (int r = 0; r < 4; ++r) {
            int row = row_base + r;
            if (row < n) {
#pragma unroll
                for (int i = 0; i < 8; ++i) {
                    int j = j0 + tx + 16*i;
                    g_X[(size_t)t*BB*GG + (size_t)row*GG + j] = acc[r][i] + bih[j] + bhh[j];
                }
            }
        }
    }
}

// ------------------------ kernel 3: gates = h @ W_hh^T (per step) ------------------------
// grid: (GG/64, 4), block 256. Tile 16(b) x 64(g), BK=32.
__global__ void gates_kernel(const float* __restrict__ Whh, int t)
{
    int n  = g_nt[t];
    int m0 = blockIdx.y * 16;
    if (m0 >= n) return;
    int j0 = blockIdx.x * 64;

    __shared__ float As[32][17];
    __shared__ float Bs[32][65];

    int tid = threadIdx.x;
    int col = tid & 63;
    int rq  = tid >> 6;            // 0..3 -> rows rq*4..rq*4+3

    int arow = tid >> 4;           // 0..15
    int ak   = (tid & 15) * 2;     // 0..30
    int bn   = tid >> 2;           // 0..63
    int bk   = (tid & 3) * 8;      // 0,8,16,24
    const float* aptr = g_h + (size_t)(m0 + arow) * HD;
    const float* bptr = Whh + (size_t)(j0 + bn) * HD;

    float acc[4] = {0.f,0.f,0.f,0.f};

    for (int k0 = 0; k0 < HD; k0 += 32) {
        float2 av = *(const float2*)(aptr + k0 + ak);
        float4 b0 = *(const float4*)(bptr + k0 + bk);
        float4 b1 = *(const float4*)(bptr + k0 + bk + 4);
        __syncthreads();
        As[ak][arow] = av.x; As[ak+1][arow] = av.y;
        Bs[bk+0][bn]=b0.x; Bs[bk+1][bn]=b0.y; Bs[bk+2][bn]=b0.z; Bs[bk+3][bn]=b0.w;
        Bs[bk+4][bn]=b1.x; Bs[bk+5][bn]=b1.y; Bs[bk+6][bn]=b1.z; Bs[bk+7][bn]=b1.w;
        __syncthreads();
#pragma unroll
        for (int k = 0; k < 32; ++k) {
            float bv = Bs[k][col];
            acc[0] += As[k][rq*4+0]*bv;
            acc[1] += As[k][rq*4+1]*bv;
            acc[2] += As[k][rq*4+2]*bv;
            acc[3] += As[k][rq*4+3]*bv;
        }
    }
#pragma unroll
    for (int r = 0; r < 4; ++r) {
        int row = m0 + rq*4 + r;
        if (row < n) g_gates[(size_t)row*GG + j0 + col] = acc[r];
    }
}

// ------------------------ kernel 4: LSTM pointwise update (per step) ------------------------
__global__ void update_kernel(int t)
{
    int idx = blockIdx.x * blockDim.x + threadIdx.x;   // 64*512
    int b = idx >> 9, k = idx & (HD-1);
    int n = g_nt[t];
    if (b >= n) return;
    const float* gx = g_X + (size_t)t*BB*GG + (size_t)b*GG;
    const float* gg = g_gates + (size_t)b*GG;
    float zi = gg[k]        + gx[k];
    float zf = gg[HD  + k]  + gx[HD  + k];
    float zg = gg[2*HD + k] + gx[2*HD + k];
    float zo = gg[3*HD + k] + gx[3*HD + k];
    float i  = 1.f / (1.f + expf(-zi));
    float f  = 1.f / (1.f + expf(-zf));
    float g  = tanhf(zg);
    float o  = 1.f / (1.f + expf(-zo));
    float c  = g_c[idx];
    float cn = f*c + i*g;
    float hn = o * tanhf(cn);
    g_c[idx] = cn;
    g_h[idx] = hn;
    g_Hbuf[(size_t)t*BB*HD + idx] = hn;
}

// ------------------------ kernel 5: predictions = Hbuf @ lin_W^T + lin_b ------------------------
// grid: (VV/128, TDEC), block 256. Tile 64(b) x 128(v), BK=16. Writes zeros for inactive rows.
__global__ void classifier_kernel(const float* __restrict__ linW,
                                  const float* __restrict__ linb,
                                  float* __restrict__ out)
{
    int t  = blockIdx.y;
    int v0 = blockIdx.x * 128;
    int n  = g_nt[t];

    int tid = threadIdx.x;
    int tx = tid & 15, ty = tid >> 4;
    int row_base = ty * 4;

    if (n == 0) {
#pragma unroll
        for (int r = 0; r < 4; ++r) {
            size_t base = (size_t)(row_base + r) * ((size_t)TDEC*VV) + (size_t)t*VV + v0;
#pragma unroll
            for (int i = 0; i < 8; ++i) out[base + tx + 16*i] = 0.f;
        }
        return;
    }

    __shared__ float As[16][65];
    __shared__ float Bs[16][129];

    bool docomp = (row_base < n);

    int lrow = tid >> 2;
    int lk4  = (tid & 3) * 4;
    const float* arow = g_Hbuf + (size_t)t*BB*HD + (size_t)lrow*HD;

    int ln = tid >> 1;
    int lh = (tid & 1) * 8;
    const float* brow = linW + (size_t)(v0 + ln) * HD;

    float acc[4][8];
#pragma unroll
    for (int r = 0; r < 4; ++r)
#pragma unroll
        for (int i = 0; i < 8; ++i) acc[r][i] = 0.f;

    for (int k0 = 0; k0 < HD; k0 += 16) {
        float4 av  = *(const float4*)(arow + k0 + lk4);
        float4 bv0 = *(const float4*)(brow + k0 + lh);
        float4 bv1 = *(const float4*)(brow + k0 + lh + 4);
        __syncthreads();
        As[lk4+0][lrow]=av.x; As[lk4+1][lrow]=av.y; As[lk4+2][lrow]=av.z; As[lk4+3][lrow]=av.w;
        Bs[lh+0][ln]=bv0.x; Bs[lh+1][ln]=bv0.y; Bs[lh+2][ln]=bv0.z; Bs[lh+3][ln]=bv0.w;
        Bs[lh+4][ln]=bv1.x; Bs[lh+5][ln]=bv1.y; Bs[lh+6][ln]=bv1.z; Bs[lh+7][ln]=bv1.w;
        __syncthreads();
        if (docomp) {
#pragma unroll
            for (int k = 0; k < 16; ++k) {
                float a0 = As[k][row_base+0], a1 = As[k][row_base+1];
                float a2 = As[k][row_base+2], a3 = As[k][row_base+3];
#pragma unroll
                for (int i = 0; i < 8; ++i) {
                    float bv = Bs[k][tx + 16*i];
                    acc[0][i] += a0*bv; acc[1][i] += a1*bv;
                    acc[2][i] += a2*bv; acc[3][i] += a3*bv;
                }
            }
        }
    }

#pragma unroll
    for (int r = 0; r < 4; ++r) {
        int row = row_base + r;
        size_t base = (size_t)row * ((size_t)TDEC*VV) + (size_t)t*VV + v0;
#pragma unroll
        for (int i = 0; i < 8; ++i) {
            int v = v0 + tx + 16*i;
            float val = (row < n) ? (acc[r][i] + linb[v]) : 0.f;
            out[base + tx + 16*i] = val;
        }
    }
}

// ------------------------ launch ------------------------
extern "C" void kernel_launch(void* const* d_in, const int* in_sizes, int n_in,
                              void* d_out, int out_size)
{
    const float* img  = (const float*)d_in[0];
    const int*   caps = (const int*)  d_in[1];
    const int*   lens = (const int*)  d_in[2];
    const float* embW = (const float*)d_in[3];
    const float* Wih  = (const float*)d_in[4];
    const float* Whh  = (const float*)d_in[5];
    const float* bih  = (const float*)d_in[6];
    const float* bhh  = (const float*)d_in[7];
    const float* linW = (const float*)d_in[8];
    const float* linb = (const float*)d_in[9];
    float* out = (float*)d_out;

    setup_kernel<<<1, 256>>>(img, caps, lens, out, out_size);
    xgate_kernel<<<dim3(GG/128, TDEC), 256>>>(embW, Wih, bih, bhh);
    for (int t = 0; t < TDEC; ++t) {
        gates_kernel<<<dim3(GG/64, 4), 256>>>(Whh, t);
        update_kernel<<<(BB*HD)/256, 256>>>(t);
    }
    classifier_kernel<<<dim3(VV/128, TDEC), 256>>>(linW, linb, out);
}

// round 2
// speedup vs baseline: 1.4387x; 1.4387x over previous
#include <cuda_runtime.h>
#include <math.h>

#define BB   64
#define TT   52
#define TDEC 51
#define HD   512
#define EE   512
#define GG   2048
#define VV   32000
#define PRED_ELEMS (BB*TDEC*VV)
#define MAXP (BB*TDEC)
#define NBLK 128

// ------------------------ device scratch ------------------------
__device__ int   g_sort_ind[BB];
__device__ int   g_declen[BB];
__device__ int   g_nt[TDEC];
__device__ int   g_pbase[TDEC];
__device__ int   g_pcount;
__device__ int   g_caps[BB*TT];
__device__ int   g_pt[MAXP];
__device__ int   g_pb[MAXP];
__device__ int   g_pcap[MAXP];
__device__ float g_h[BB*HD];
__device__ float g_gates[BB*GG];
__device__ float g_X[(size_t)TDEC*BB*GG];
__device__ float g_Hpk[(size_t)MAXP*HD];
__device__ unsigned g_bar_count;
__device__ volatile unsigned g_bar_sense;

// ------------------------ helpers ------------------------
__device__ __forceinline__ float to_tf32(float x) {
    float r; asm("cvt.rna.tf32.f32 %0, %1;" : "=f"(r) : "f"(x)); return r;
}
__device__ __forceinline__ void st4_tf32(float* d, float4 r) {
    d[0]=to_tf32(r.x); d[1]=to_tf32(r.y); d[2]=to_tf32(r.z); d[3]=to_tf32(r.w);
}
__device__ __forceinline__ void st4_split(float* dh, float* dl, float4 r) {
    float h;
    h=to_tf32(r.x); dh[0]=h; dl[0]=to_tf32(r.x-h);
    h=to_tf32(r.y); dh[1]=h; dl[1]=to_tf32(r.y-h);
    h=to_tf32(r.z); dh[2]=h; dl[2]=to_tf32(r.z-h);
    h=to_tf32(r.w); dh[3]=h; dl[3]=to_tf32(r.w-h);
}
__device__ __forceinline__ void mma8(float* d, const float* a, const float* b) {
    asm volatile("mma.sync.aligned.m16n8k8.row.col.f32.tf32.tf32.f32 "
        "{%0,%1,%2,%3}, {%4,%5,%6,%7}, {%8,%9}, {%0,%1,%2,%3};"
        : "+f"(d[0]), "+f"(d[1]), "+f"(d[2]), "+f"(d[3])
        : "r"(__float_as_uint(a[0])), "r"(__float_as_uint(a[1])),
          "r"(__float_as_uint(a[2])), "r"(__float_as_uint(a[3])),
          "r"(__float_as_uint(b[0])), "r"(__float_as_uint(b[1])));
}
__device__ __forceinline__ void gridbar(unsigned gen) {
    __threadfence();
    __syncthreads();
    if (threadIdx.x == 0) {
        if (atomicAdd(&g_bar_count, 1u) == NBLK - 1u) {
            g_bar_count = 0u;
            __threadfence();
            g_bar_sense = gen;
        } else {
            while (g_bar_sense != gen) { }
            __threadfence();
        }
    }
    __syncthreads();
}

// ------------------------ kernel 1: sort + gathers + pair maps ------------------------
__global__ void setup_kernel(const float* __restrict__ img,
                             const int*   __restrict__ caps_in,
                             const int*   __restrict__ lens,
                             float* __restrict__ out, int out_elems)
{
    __shared__ int s_len[BB];
    int tid = threadIdx.x;
    if (tid < BB) s_len[tid] = lens[tid];
    __syncthreads();

    if (tid == 0) {
        unsigned long long used = 0ull;
        for (int p = 0; p < BB; ++p) {
            int best = -1, bl = -1000000;
            for (int j = 0; j < BB; ++j)
                if (!((used >> j) & 1ull) && s_len[j] > bl) { bl = s_len[j]; best = j; }
            used |= 1ull << best;
            g_sort_ind[p] = best;
            g_declen[p]   = bl - 1;
        }
        g_bar_count = 0u;
        g_bar_sense = 0u;
    }
    __syncthreads();

    if (tid < TDEC) {
        int cnt = 0;
        for (int p = 0; p < BB; ++p) cnt += (g_declen[p] > tid) ? 1 : 0;
        g_nt[tid] = cnt;
    }

    bool wt = (out_elems >= PRED_ELEMS + BB*TT + 2*BB);
    for (int idx = tid; idx < BB*TT; idx += blockDim.x) {
        int p = idx / TT, j = idx - p*TT;
        int c = caps_in[g_sort_ind[p]*TT + j];
        g_caps[idx] = c;
        if (wt) out[PRED_ELEMS + idx] = (float)c;
    }
    for (int idx = tid; idx < BB*HD; idx += blockDim.x) {
        int p = idx >> 9;
        g_h[idx] = img[g_sort_ind[p]*HD + (idx & (HD-1))];
    }
    if (wt && tid < BB) {
        out[PRED_ELEMS + BB*TT + tid]      = (float)g_declen[tid];
        out[PRED_ELEMS + BB*TT + BB + tid] = (float)g_sort_ind[tid];
    }
    __syncthreads();
    if (tid == 0) {
        int pb = 0;
        for (int t = 0; t < TDEC; ++t) { g_pbase[t] = pb; pb += g_nt[t]; }
        g_pcount = pb;
    }
    __syncthreads();
    if (tid < TDEC) {
        int n = g_nt[tid], pb = g_pbase[tid];
        for (int b = 0; b < n; ++b) {
            g_pt[pb+b]   = tid;
            g_pb[pb+b]   = b;
            g_pcap[pb+b] = g_caps[b*TT + tid];
        }
    }
}

// ------------------------ kernel 2: zero-fill inactive rows ------------------------
__global__ void zerofill_kernel(float* __restrict__ out)
{
    int bid = blockIdx.x;
    int b = bid / TDEC, t = bid - b*TDEC;
    if (t < g_declen[b]) return;
    float4 z = make_float4(0.f,0.f,0.f,0.f);
    float4* dst = (float4*)(out + ((size_t)b*TDEC + t)*VV);
    for (int i = threadIdx.x; i < VV/4; i += blockDim.x) dst[i] = z;
}

// ------------------------ kernel 3: xgate via tf32x3 mma ------------------------
// X[p][j] = emb[pcap[p]] . Wih[j] + bih[j] + bhh[j], stored at g_X[t][b][j]
__global__ void __launch_bounds__(256) xgate_mma(const float* __restrict__ embW,
                                                const float* __restrict__ Wih,
                                                const float* __restrict__ bih,
                                                const float* __restrict__ bhh)
{
    int P  = g_pcount;
    int m0 = blockIdx.y * 128;
    if (m0 >= P) return;
    int j0 = blockIdx.x * 128;

    __shared__ float Ah[128][20], Al[128][20], Bh[128][20], Bl[128][20];

    int tid  = threadIdx.x;
    int lane = tid & 31, wid = tid >> 5;
    int wm = wid & 1, wn = wid >> 1;
    int gq = lane >> 2, tig = lane & 3;

    int lrow = tid >> 2;
    int lkq  = (tid & 3) * 4;
    int p0 = m0 + lrow, p1 = m0 + lrow + 64;
    bool va0 = p0 < P, va1 = p1 < P;
    const float* a0p = va0 ? (embW + (size_t)g_pcap[p0]*EE + lkq) : (embW + lkq);
    const float* a1p = va1 ? (embW + (size_t)g_pcap[p1]*EE + lkq) : (embW + lkq);
    const float* b0p = Wih + (size_t)(j0+lrow)*EE + lkq;
    const float* b1p = Wih + (size_t)(j0+lrow+64)*EE + lkq;

    float acc[4][4][4];
#pragma unroll
    for (int i=0;i<4;i++)
#pragma unroll
        for (int j=0;j<4;j++)
#pragma unroll
            for (int q=0;q<4;q++) acc[i][j][q] = 0.f;

    for (int kc = 0; kc < 32; ++kc) {
        int k0 = kc*16;
        float4 ra0 = va0 ? *(const float4*)(a0p + k0) : make_float4(0,0,0,0);
        float4 ra1 = va1 ? *(const float4*)(a1p + k0) : make_float4(0,0,0,0);
        float4 rb0 = *(const float4*)(b0p + k0);
        float4 rb1 = *(const float4*)(b1p + k0);
        __syncthreads();
        st4_split(&Ah[lrow][lkq],    &Al[lrow][lkq],    ra0);
        st4_split(&Ah[lrow+64][lkq], &Al[lrow+64][lkq], ra1);
        st4_split(&Bh[lrow][lkq],    &Bl[lrow][lkq],    rb0);
        st4_split(&Bh[lrow+64][lkq], &Bl[lrow+64][lkq], rb1);
        __syncthreads();
#pragma unroll
        for (int k8 = 0; k8 < 2; ++k8) {
            int kb = k8*8;
            float ah[4][4], al[4][4], bh[4][2], bl[4][2];
#pragma unroll
            for (int mt=0;mt<4;mt++) {
                int rm = wm*64 + mt*16;
                ah[mt][0]=Ah[rm+gq][kb+tig];   ah[mt][1]=Ah[rm+gq+8][kb+tig];
                ah[mt][2]=Ah[rm+gq][kb+tig+4]; ah[mt][3]=Ah[rm+gq+8][kb+tig+4];
                al[mt][0]=Al[rm+gq][kb+tig];   al[mt][1]=Al[rm+gq+8][kb+tig];
                al[mt][2]=Al[rm+gq][kb+tig+4]; al[mt][3]=Al[rm+gq+8][kb+tig+4];
            }
#pragma unroll
            for (int nt=0;nt<4;nt++) {
                int rn = wn*32 + nt*8;
                bh[nt][0]=Bh[rn+gq][kb+tig]; bh[nt][1]=Bh[rn+gq][kb+tig+4];
                bl[nt][0]=Bl[rn+gq][kb+tig]; bl[nt][1]=Bl[rn+gq][kb+tig+4];
            }
#pragma unroll
            for (int mt=0;mt<4;mt++)
#pragma unroll
                for (int nt=0;nt<4;nt++) {
                    mma8(acc[mt][nt], ah[mt], bh[nt]);
                    mma8(acc[mt][nt], ah[mt], bl[nt]);
                    mma8(acc[mt][nt], al[mt], bh[nt]);
                }
        }
    }

    float2 lb[4];
#pragma unroll
    for (int nt=0;nt<4;nt++) {
        int v = j0 + wn*32 + nt*8 + tig*2;
        float2 bi = *(const float2*)(bih + v);
        float2 bh2 = *(const float2*)(bhh + v);
        lb[nt].x = bi.x + bh2.x; lb[nt].y = bi.y + bh2.y;
    }
#pragma unroll
    for (int mt=0;mt<4;mt++) {
#pragma unroll
        for (int half=0; half<2; ++half) {
            int ml = wm*64 + mt*16 + gq + half*8;
            int p = m0 + ml;
            if (p < P) {
                int tt = g_pt[p], bb = g_pb[p];
                size_t base = (size_t)tt*BB*GG + (size_t)bb*GG + j0 + wn*32 + tig*2;
#pragma unroll
                for (int nt=0;nt<4;nt++) {
                    float2 val;
                    val.x = acc[mt][nt][half*2+0] + lb[nt].x;
                    val.y = acc[mt][nt][half*2+1] + lb[nt].y;
                    *(float2*)(g_X + base + nt*8) = val;
                }
            }
        }
    }
}

// ------------------------ kernel 4: persistent LSTM recurrence ------------------------
__global__ void __launch_bounds__(256) recur_kernel(const float* __restrict__ Whh)
{
    __shared__ float sW[HD][16];
    int tid = threadIdx.x;
    int blk = blockIdx.x;
    int c0 = blk * 16;
    for (int idx = tid; idx < 16*HD; idx += 256) {
        int c = idx >> 9, k = idx & (HD-1);
        sW[k][c] = Whh[(size_t)(c0 + c)*HD + k];
    }
    int rgrp = tid >> 4;          // 0..15 -> rows rgrp*4..+3
    int cc   = tid & 15;
    int eb   = blk*256 + tid;
    int b_u  = eb >> 9, k_u = eb & (HD-1);
    float creg = 0.f;
    unsigned gen = 0;
    __syncthreads();

    for (int t = 0; t < TDEC; ++t) {
        int n = g_nt[t];
        int r0 = rgrp*4;
        if (r0 < n) {
            float a0=0.f,a1=0.f,a2=0.f,a3=0.f;
            const float4* h0 = (const float4*)(g_h + (size_t)(r0+0)*HD);
            const float4* h1 = (const float4*)(g_h + (size_t)(r0+1)*HD);
            const float4* h2 = (const float4*)(g_h + (size_t)(r0+2)*HD);
            const float4* h3 = (const float4*)(g_h + (size_t)(r0+3)*HD);
#pragma unroll 4
            for (int kq = 0; kq < HD/4; ++kq) {
                float4 v0 = __ldcg(h0+kq), v1 = __ldcg(h1+kq);
                float4 v2 = __ldcg(h2+kq), v3 = __ldcg(h3+kq);
                float w0 = sW[4*kq][cc], w1 = sW[4*kq+1][cc];
                float w2 = sW[4*kq+2][cc], w3 = sW[4*kq+3][cc];
                a0 += v0.x*w0; a1 += v1.x*w0; a2 += v2.x*w0; a3 += v3.x*w0;
                a0 += v0.y*w1; a1 += v1.y*w1; a2 += v2.y*w1; a3 += v3.y*w1;
                a0 += v0.z*w2; a1 += v1.z*w2; a2 += v2.z*w2; a3 += v3.z*w2;
                a0 += v0.w*w3; a1 += v1.w*w3; a2 += v2.w*w3; a3 += v3.w*w3;
            }
            int col = c0 + cc;
            if (r0+0 < n) g_gates[(size_t)(r0+0)*GG + col] = a0;
            if (r0+1 < n) g_gates[(size_t)(r0+1)*GG + col] = a1;
            if (r0+2 < n) g_gates[(size_t)(r0+2)*GG + col] = a2;
            if (r0+3 < n) g_gates[(size_t)(r0+3)*GG + col] = a3;
        }
        gen++; gridbar(gen);

        if (b_u < n) {
            const float* gx = g_X + (size_t)t*BB*GG + (size_t)b_u*GG + k_u;
            const float* gr = g_gates + (size_t)b_u*GG + k_u;
            float zi = __ldcg(gr)        + gx[0];
            float zf = __ldcg(gr +   HD) + gx[HD];
            float zg = __ldcg(gr + 2*HD) + gx[2*HD];
            float zo = __ldcg(gr + 3*HD) + gx[3*HD];
            float ii = 1.f/(1.f+expf(-zi));
            float ff = 1.f/(1.f+expf(-zf));
            float gv = tanhf(zg);
            float oo = 1.f/(1.f+expf(-zo));
            creg = ff*creg + ii*gv;
            float hn = oo * tanhf(creg);
            g_h[(size_t)b_u*HD + k_u] = hn;
            g_Hpk[(size_t)(g_pbase[t] + b_u)*HD + k_u] = hn;
        }
        gen++; gridbar(gen);
    }
}

// ------------------------ kernel 5: classifier via tf32 mma ------------------------
__global__ void __launch_bounds__(256) classifier_mma(const float* __restrict__ linW,
                                                      const float* __restrict__ linb,
                                                      float* __restrict__ out)
{
    int P  = g_pcount;
    int m0 = blockIdx.y * 128;
    if (m0 >= P) return;
    int v0 = blockIdx.x * 128;

    __shared__ float As[128][20];
    __shared__ float Bs[128][20];

    int tid  = threadIdx.x;
    int lane = tid & 31, wid = tid >> 5;
    int wm = wid & 1, wn = wid >> 1;
    int gq = lane >> 2, tig = lane & 3;

    int lrow = tid >> 2;
    int lkq  = (tid & 3) * 4;
    int p0 = m0 + lrow, p1 = m0 + lrow + 64;
    bool va0 = p0 < P, va1 = p1 < P;
    const float* a0p = g_Hpk + (size_t)p0*HD + lkq;
    const float* a1p = g_Hpk + (size_t)p1*HD + lkq;
    const float* b0p = linW + (size_t)(v0+lrow)*HD + lkq;
    const float* b1p = linW + (size_t)(v0+lrow+64)*HD + lkq;

    float acc[4][4][4];
#pragma unroll
    for (int i=0;i<4;i++)
#pragma unroll
        for (int j=0;j<4;j++)
#pragma unroll
            for (int q=0;q<4;q++) acc[i][j][q] = 0.f;

    float4 ra0 = va0 ? *(const float4*)(a0p) : make_float4(0,0,0,0);
    float4 ra1 = va1 ? *(const float4*)(a1p) : make_float4(0,0,0,0);
    float4 rb0 = *(const float4*)(b0p);
    float4 rb1 = *(const float4*)(b1p);
    st4_tf32(&As[lrow][lkq],    ra0);
    st4_tf32(&As[lrow+64][lkq], ra1);
    st4_tf32(&Bs[lrow][lkq],    rb0);
    st4_tf32(&Bs[lrow+64][lkq], rb1);
    __syncthreads();

    for (int kc = 0; kc < 32; ++kc) {
        int kn = (kc+1)*16;
        if (kc < 31) {
            ra0 = va0 ? *(const float4*)(a0p + kn) : make_float4(0,0,0,0);
            ra1 = va1 ? *(const float4*)(a1p + kn) : make_float4(0,0,0,0);
            rb0 = *(const float4*)(b0p + kn);
            rb1 = *(const float4*)(b1p + kn);
        }
#pragma unroll
        for (int k8 = 0; k8 < 2; ++k8) {
            int kb = k8*8;
            float af[4][4], bf[4][2];
#pragma unroll
            for (int mt=0;mt<4;mt++) {
                int rm = wm*64 + mt*16;
                af[mt][0]=As[rm+gq][kb+tig];   af[mt][1]=As[rm+gq+8][kb+tig];
                af[mt][2]=As[rm+gq][kb+tig+4]; af[mt][3]=As[rm+gq+8][kb+tig+4];
            }
#pragma unroll
            for (int nt=0;nt<4;nt++) {
                int rn = wn*32 + nt*8;
                bf[nt][0]=Bs[rn+gq][kb+tig]; bf[nt][1]=Bs[rn+gq][kb+tig+4];
            }
#pragma unroll
            for (int mt=0;mt<4;mt++)
#pragma unroll
                for (int nt=0;nt<4;nt++)
                    mma8(acc[mt][nt], af[mt], bf[nt]);
        }
        __syncthreads();
        if (kc < 31) {
            st4_tf32(&As[lrow][lkq],    ra0);
            st4_tf32(&As[lrow+64][lkq], ra1);
            st4_tf32(&Bs[lrow][lkq],    rb0);
            st4_tf32(&Bs[lrow+64][lkq], rb1);
            __syncthreads();
        }
    }

    float2 lb[4];
#pragma unroll
    for (int nt=0;nt<4;nt++) {
        int v = v0 + wn*32 + nt*8 + tig*2;
        lb[nt] = *(const float2*)(linb + v);
    }
#pragma unroll
    for (int mt=0;mt<4;mt++) {
#pragma unroll
        for (int half=0; half<2; ++half) {
            int ml = wm*64 + mt*16 + gq + half*8;
            int p = m0 + ml;
            if (p < P) {
                int tt = g_pt[p], bb = g_pb[p];
                size_t base = ((size_t)bb*TDEC + tt)*VV + v0 + wn*32 + tig*2;
#pragma unroll
                for (int nt=0;nt<4;nt++) {
                    float2 val;
                    val.x = acc[mt][nt][half*2+0] + lb[nt].x;
                    val.y = acc[mt][nt][half*2+1] + lb[nt].y;
                    *(float2*)(out + base + nt*8) = val;
                }
            }
        }
    }
}

// ------------------------ launch ------------------------
extern "C" void kernel_launch(void* const* d_in, const int* in_sizes, int n_in,
                              void* d_out, int out_size)
{
    const float* img  = (const float*)d_in[0];
    const int*   caps = (const int*)  d_in[1];
    const int*   lens = (const int*)  d_in[2];
    const float* embW = (const float*)d_in[3];
    const float* Wih  = (const float*)d_in[4];
    const float* Whh  = (const float*)d_in[5];
    const float* bih  = (const float*)d_in[6];
    const float* bhh  = (const float*)d_in[7];
    const float* linW = (const float*)d_in[8];
    const float* linb = (const float*)d_in[9];
    float* out = (float*)d_out;

    setup_kernel<<<1, 256>>>(img, caps, lens, out, out_size);
    zerofill_kernel<<<BB*TDEC, 256>>>(out);
    xgate_mma<<<dim3(GG/128, (MAXP+127)/128), 256>>>(embW, Wih, bih, bhh);
    recur_kernel<<<NBLK, 256>>>(Whh);
    classifier_mma<<<dim3(VV/128, (MAXP+127)/128), 256>>>(linW, linb, out);
}

// round 5
// speedup vs baseline: 1.4845x; 1.0318x over previous
#include <cuda_runtime.h>
#include <stdint.h>
#include <math.h>

#define BB   64
#define TT   52
#define TDEC 51
#define HD   512
#define EE   512
#define GG   2048
#define VV   32000
#define PRED_ELEMS (BB*TDEC*VV)
#define MAXP (BB*TDEC)
#define NBLK 128

// ------------------------ device scratch ------------------------
__device__ int   g_sort_ind[BB];
__device__ int   g_declen[BB];
__device__ int   g_nt[TDEC];
__device__ int   g_pbase[TDEC];
__device__ int   g_pcount;
__device__ int   g_caps[BB*TT];
__device__ int   g_pt[MAXP];
__device__ int   g_pb[MAXP];
__device__ int   g_pcap[MAXP];
__device__ float g_h[BB*HD];
__device__ float g_gates[BB*GG];
__device__ float g_X[(size_t)TDEC*BB*GG];
__device__ float g_Hpk[(size_t)MAXP*HD];          // tf32-rounded h history
__device__ float g_linWr[(size_t)VV*HD];          // tf32-rounded lin_W (64MB)
__device__ unsigned g_bar_count;
__device__ unsigned g_bar_sense;

// ------------------------ helpers ------------------------
__device__ __forceinline__ float to_tf32(float x) {
    float r; asm("cvt.rna.tf32.f32 %0, %1;" : "=f"(r) : "f"(x)); return r;
}
__device__ __forceinline__ void st4_split(float* dh, float* dl, float4 r) {
    float h;
    h=to_tf32(r.x); dh[0]=h; dl[0]=to_tf32(r.x-h);
    h=to_tf32(r.y); dh[1]=h; dl[1]=to_tf32(r.y-h);
    h=to_tf32(r.z); dh[2]=h; dl[2]=to_tf32(r.z-h);
    h=to_tf32(r.w); dh[3]=h; dl[3]=to_tf32(r.w-h);
}
__device__ __forceinline__ void mma8(float* d, const float* a, const float* b) {
    asm volatile("mma.sync.aligned.m16n8k8.row.col.f32.tf32.tf32.f32 "
        "{%0,%1,%2,%3}, {%4,%5,%6,%7}, {%8,%9}, {%0,%1,%2,%3};"
        : "+f"(d[0]), "+f"(d[1]), "+f"(d[2]), "+f"(d[3])
        : "r"(__float_as_uint(a[0])), "r"(__float_as_uint(a[1])),
          "r"(__float_as_uint(a[2])), "r"(__float_as_uint(a[3])),
          "r"(__float_as_uint(b[0])), "r"(__float_as_uint(b[1])));
}
__device__ __forceinline__ void cpasync16(uint32_t saddr, const float* gptr) {
    asm volatile("cp.async.cg.shared.global [%0], [%1], 16;"
                 :: "r"(saddr), "l"(gptr) : "memory");
}
__device__ __forceinline__ void gridbar(unsigned gen) {
    __syncthreads();
    if (threadIdx.x == 0) {
        unsigned prev;
        asm volatile("atom.release.gpu.global.add.u32 %0, [%1], 1;"
                     : "=r"(prev) : "l"(&g_bar_count) : "memory");
        if (prev == NBLK - 1u) {
            g_bar_count = 0u;
            asm volatile("st.release.gpu.global.u32 [%0], %1;"
                         :: "l"(&g_bar_sense), "r"(gen) : "memory");
        } else {
            unsigned s;
            do {
                asm volatile("ld.acquire.gpu.global.u32 %0, [%1];"
                             : "=r"(s) : "l"(&g_bar_sense) : "memory");
            } while (s != gen);
        }
    }
    __syncthreads();
}

// ------------------------ kernel 1: sort + gathers + pair maps ------------------------
__global__ void setup_kernel(const float* __restrict__ img,
                             const int*   __restrict__ caps_in,
                             const int*   __restrict__ lens,
                             float* __restrict__ out, int out_elems)
{
    __shared__ int s_len[BB];
    int tid = threadIdx.x;
    if (tid < BB) s_len[tid] = lens[tid];
    __syncthreads();

    if (tid == 0) {
        unsigned long long used = 0ull;
        for (int p = 0; p < BB; ++p) {
            int best = -1, bl = -1000000;
            for (int j = 0; j < BB; ++j)
                if (!((used >> j) & 1ull) && s_len[j] > bl) { bl = s_len[j]; best = j; }
            used |= 1ull << best;
            g_sort_ind[p] = best;
            g_declen[p]   = bl - 1;
        }
        g_bar_count = 0u;
        g_bar_sense = 0u;
    }
    __syncthreads();

    if (tid < TDEC) {
        int cnt = 0;
        for (int p = 0; p < BB; ++p) cnt += (g_declen[p] > tid) ? 1 : 0;
        g_nt[tid] = cnt;
    }

    bool wt = (out_elems >= PRED_ELEMS + BB*TT + 2*BB);
    for (int idx = tid; idx < BB*TT; idx += blockDim.x) {
        int p = idx / TT, j = idx - p*TT;
        int c = caps_in[g_sort_ind[p]*TT + j];
        g_caps[idx] = c;
        if (wt) out[PRED_ELEMS + idx] = (float)c;
    }
    for (int idx = tid; idx < BB*HD; idx += blockDim.x) {
        int p = idx >> 9;
        g_h[idx] = img[g_sort_ind[p]*HD + (idx & (HD-1))];
    }
    if (wt && tid < BB) {
        out[PRED_ELEMS + BB*TT + tid]      = (float)g_declen[tid];
        out[PRED_ELEMS + BB*TT + BB + tid] = (float)g_sort_ind[tid];
    }
    __syncthreads();
    if (tid == 0) {
        int pb = 0;
        for (int t = 0; t < TDEC; ++t) { g_pbase[t] = pb; pb += g_nt[t]; }
        g_pcount = pb;
    }
    __syncthreads();
    if (tid < TDEC) {
        int n = g_nt[tid], pb = g_pbase[tid];
        for (int b = 0; b < n; ++b) {
            g_pt[pb+b]   = tid;
            g_pb[pb+b]   = b;
            g_pcap[pb+b] = g_caps[b*TT + tid];
        }
    }
}

// ------------------------ kernel 1b: pre-round linW to tf32 ------------------------
__global__ void round_linW(const float* __restrict__ w)
{
    size_t i = (size_t)blockIdx.x * blockDim.x + threadIdx.x;
    const float4* src = (const float4*)w;
    float4 v = src[i];
    v.x = to_tf32(v.x); v.y = to_tf32(v.y); v.z = to_tf32(v.z); v.w = to_tf32(v.w);
    ((float4*)g_linWr)[i] = v;
}

// ------------------------ kernel 2: zero-fill inactive rows ------------------------
__global__ void zerofill_kernel(float* __restrict__ out)
{
    int bid = blockIdx.x;
    int b = bid / TDEC, t = bid - b*TDEC;
    if (t < g_declen[b]) return;
    float4 z = make_float4(0.f,0.f,0.f,0.f);
    float4* dst = (float4*)(out + ((size_t)b*TDEC + t)*VV);
    for (int i = threadIdx.x; i < VV/4; i += blockDim.x) dst[i] = z;
}

// ------------------------ kernel 3: xgate via tf32x3 mma ------------------------
__global__ void __launch_bounds__(256) xgate_mma(const float* __restrict__ embW,
                                                const float* __restrict__ Wih,
                                                const float* __restrict__ bih,
                                                const float* __restrict__ bhh)
{
    int P  = g_pcount;
    int m0 = blockIdx.y * 128;
    if (m0 >= P) return;
    int j0 = blockIdx.x * 128;

    __shared__ float Ah[128][20], Al[128][20], Bh[128][20], Bl[128][20];

    int tid  = threadIdx.x;
    int lane = tid & 31, wid = tid >> 5;
    int wm = wid & 1, wn = wid >> 1;
    int gq = lane >> 2, tig = lane & 3;

    int lrow = tid >> 2;
    int lkq  = (tid & 3) * 4;
    int p0 = m0 + lrow, p1 = m0 + lrow + 64;
    bool va0 = p0 < P, va1 = p1 < P;
    const float* a0p = va0 ? (embW + (size_t)g_pcap[p0]*EE + lkq) : (embW + lkq);
    const float* a1p = va1 ? (embW + (size_t)g_pcap[p1]*EE + lkq) : (embW + lkq);
    const float* b0p = Wih + (size_t)(j0+lrow)*EE + lkq;
    const float* b1p = Wih + (size_t)(j0+lrow+64)*EE + lkq;

    float acc[4][4][4];
#pragma unroll
    for (int i=0;i<4;i++)
#pragma unroll
        for (int j=0;j<4;j++)
#pragma unroll
            for (int q=0;q<4;q++) acc[i][j][q] = 0.f;

    for (int kc = 0; kc < 32; ++kc) {
        int k0 = kc*16;
        float4 ra0 = va0 ? *(const float4*)(a0p + k0) : make_float4(0,0,0,0);
        float4 ra1 = va1 ? *(const float4*)(a1p + k0) : make_float4(0,0,0,0);
        float4 rb0 = *(const float4*)(b0p + k0);
        float4 rb1 = *(const float4*)(b1p + k0);
        __syncthreads();
        st4_split(&Ah[lrow][lkq],    &Al[lrow][lkq],    ra0);
        st4_split(&Ah[lrow+64][lkq], &Al[lrow+64][lkq], ra1);
        st4_split(&Bh[lrow][lkq],    &Bl[lrow][lkq],    rb0);
        st4_split(&Bh[lrow+64][lkq], &Bl[lrow+64][lkq], rb1);
        __syncthreads();
#pragma unroll
        for (int k8 = 0; k8 < 2; ++k8) {
            int kb = k8*8;
            float ah[4][4], al[4][4], bh[4][2], bl[4][2];
#pragma unroll
            for (int mt=0;mt<4;mt++) {
                int rm = wm*64 + mt*16;
                ah[mt][0]=Ah[rm+gq][kb+tig];   ah[mt][1]=Ah[rm+gq+8][kb+tig];
                ah[mt][2]=Ah[rm+gq][kb+tig+4]; ah[mt][3]=Ah[rm+gq+8][kb+tig+4];
                al[mt][0]=Al[rm+gq][kb+tig];   al[mt][1]=Al[rm+gq+8][kb+tig];
                al[mt][2]=Al[rm+gq][kb+tig+4]; al[mt][3]=Al[rm+gq+8][kb+tig+4];
            }
#pragma unroll
            for (int nt=0;nt<4;nt++) {
                int rn = wn*32 + nt*8;
                bh[nt][0]=Bh[rn+gq][kb+tig]; bh[nt][1]=Bh[rn+gq][kb+tig+4];
                bl[nt][0]=Bl[rn+gq][kb+tig]; bl[nt][1]=Bl[rn+gq][kb+tig+4];
            }
#pragma unroll
            for (int mt=0;mt<4;mt++)
#pragma unroll
                for (int nt=0;nt<4;nt++) {
                    mma8(acc[mt][nt], ah[mt], bh[nt]);
                    mma8(acc[mt][nt], ah[mt], bl[nt]);
                    mma8(acc[mt][nt], al[mt], bh[nt]);
                }
        }
    }

    float2 lb[4];
#pragma unroll
    for (int nt=0;nt<4;nt++) {
        int v = j0 + wn*32 + nt*8 + tig*2;
        float2 bi = *(const float2*)(bih + v);
        float2 bh2 = *(const float2*)(bhh + v);
        lb[nt].x = bi.x + bh2.x; lb[nt].y = bi.y + bh2.y;
    }
#pragma unroll
    for (int mt=0;mt<4;mt++) {
#pragma unroll
        for (int half=0; half<2; ++half) {
            int ml = wm*64 + mt*16 + gq + half*8;
            int p = m0 + ml;
            if (p < P) {
                int tt = g_pt[p], bb = g_pb[p];
                size_t base = (size_t)tt*BB*GG + (size_t)bb*GG + j0 + wn*32 + tig*2;
#pragma unroll
                for (int nt=0;nt<4;nt++) {
                    float2 val;
                    val.x = acc[mt][nt][half*2+0] + lb[nt].x;
                    val.y = acc[mt][nt][half*2+1] + lb[nt].y;
                    *(float2*)(g_X + base + nt*8) = val;
                }
            }
        }
    }
}

// ------------------------ kernel 4: persistent LSTM recurrence ------------------------
__global__ void __launch_bounds__(256) recur_kernel(const float* __restrict__ Whh)
{
    __shared__ float sW[HD][16];
    int tid = threadIdx.x;
    int blk = blockIdx.x;
    int c0 = blk * 16;
    for (int idx = tid; idx < 16*HD; idx += 256) {
        int c = idx >> 9, k = idx & (HD-1);
        sW[k][c] = Whh[(size_t)(c0 + c)*HD + k];
    }
    int rgrp = tid >> 4;
    int cc   = tid & 15;
    int eb   = blk*256 + tid;
    int b_u  = eb >> 9, k_u = eb & (HD-1);
    float creg = 0.f;
    unsigned gen = 0;
    __syncthreads();

    for (int t = 0; t < TDEC; ++t) {
        int n = g_nt[t];
        int r0 = rgrp*4;
        if (r0 < n) {
            float a0=0.f,a1=0.f,a2=0.f,a3=0.f;
            const float4* h0 = (const float4*)(g_h + (size_t)(r0+0)*HD);
            const float4* h1 = (const float4*)(g_h + (size_t)(r0+1)*HD);
            const float4* h2 = (const float4*)(g_h + (size_t)(r0+2)*HD);
            const float4* h3 = (const float4*)(g_h + (size_t)(r0+3)*HD);
#pragma unroll 4
            for (int kq = 0; kq < HD/4; ++kq) {
                float4 v0 = __ldcg(h0+kq), v1 = __ldcg(h1+kq);
                float4 v2 = __ldcg(h2+kq), v3 = __ldcg(h3+kq);
                float w0 = sW[4*kq][cc], w1 = sW[4*kq+1][cc];
                float w2 = sW[4*kq+2][cc], w3 = sW[4*kq+3][cc];
                a0 += v0.x*w0; a1 += v1.x*w0; a2 += v2.x*w0; a3 += v3.x*w0;
                a0 += v0.y*w1; a1 += v1.y*w1; a2 += v2.y*w1; a3 += v3.y*w1;
                a0 += v0.z*w2; a1 += v1.z*w2; a2 += v2.z*w2; a3 += v3.z*w2;
                a0 += v0.w*w3; a1 += v1.w*w3; a2 += v2.w*w3; a3 += v3.w*w3;
            }
            int col = c0 + cc;
            if (r0+0 < n) g_gates[(size_t)(r0+0)*GG + col] = a0;
            if (r0+1 < n) g_gates[(size_t)(r0+1)*GG + col] = a1;
            if (r0+2 < n) g_gates[(size_t)(r0+2)*GG + col] = a2;
            if (r0+3 < n) g_gates[(size_t)(r0+3)*GG + col] = a3;
        }
        gen++; gridbar(gen);

        if (b_u < n) {
            const float* gx = g_X + (size_t)t*BB*GG + (size_t)b_u*GG + k_u;
            const float* gr = g_gates + (size_t)b_u*GG + k_u;
            float zi = __ldcg(gr)        + gx[0];
            float zf = __ldcg(gr +   HD) + gx[HD];
            float zg = __ldcg(gr + 2*HD) + gx[2*HD];
            float zo = __ldcg(gr + 3*HD) + gx[3*HD];
            float ii = 1.f/(1.f+expf(-zi));
            float ff = 1.f/(1.f+expf(-zf));
            float gv = tanhf(zg);
            float oo = 1.f/(1.f+expf(-zo));
            creg = ff*creg + ii*gv;
            float hn = oo * tanhf(creg);
            g_h[(size_t)b_u*HD + k_u] = hn;
            g_Hpk[(size_t)(g_pbase[t] + b_u)*HD + k_u] = to_tf32(hn);
        }
        gen++; gridbar(gen);
    }
}

// ------------------------ kernel 5: classifier, cp.async double-buffered tf32 mma ------------------------
__global__ void __launch_bounds__(256,2) classifier_mma(const float* __restrict__ linb,
                                                        float* __restrict__ out)
{
    int P  = g_pcount;
    int m0 = blockIdx.y * 128;
    if (m0 >= P) return;
    int v0 = blockIdx.x * 128;

    __shared__ float As[2][128][20];
    __shared__ float Bs[2][128][20];

    int tid  = threadIdx.x;
    int lane = tid & 31, wid = tid >> 5;
    int wm = wid & 1, wn = wid >> 1;
    int gq = lane >> 2, tig = lane & 3;

    int lrow = tid >> 2;
    int lkq  = (tid & 3) * 4;
    int p0 = m0 + lrow, p1 = m0 + lrow + 64;
    const float* a0p = g_Hpk + (size_t)(p0 < P ? p0 : 0)*HD + lkq;
    const float* a1p = g_Hpk + (size_t)(p1 < P ? p1 : 0)*HD + lkq;
    const float* b0p = g_linWr + (size_t)(v0+lrow)*HD + lkq;
    const float* b1p = g_linWr + (size_t)(v0+lrow+64)*HD + lkq;

    uint32_t sa0 = (uint32_t)__cvta_generic_to_shared(&As[0][lrow][lkq]);
    uint32_t sa1 = (uint32_t)__cvta_generic_to_shared(&As[0][lrow+64][lkq]);
    uint32_t sb0 = (uint32_t)__cvta_generic_to_shared(&Bs[0][lrow][lkq]);
    uint32_t sb1 = (uint32_t)__cvta_generic_to_shared(&Bs[0][lrow+64][lkq]);
    const uint32_t STG = 128*20*4;   // bytes per stage

    float acc[4][4][4];
#pragma unroll
    for (int i=0;i<4;i++)
#pragma unroll
        for (int j=0;j<4;j++)
#pragma unroll
            for (int q=0;q<4;q++) acc[i][j][q] = 0.f;

    // prologue: stage 0
    cpasync16(sa0, a0p);
    cpasync16(sa1, a1p);
    cpasync16(sb0, b0p);
    cpasync16(sb1, b1p);
    asm volatile("cp.async.commit_group;" ::: "memory");

    for (int kc = 0; kc < 32; ++kc) {
        if (kc < 31) {
            uint32_t off = ((kc+1)&1) * STG;
            int kn = (kc+1)*16;
            cpasync16(sa0 + off, a0p + kn);
            cpasync16(sa1 + off, a1p + kn);
            cpasync16(sb0 + off, b0p + kn);
            cpasync16(sb1 + off, b1p + kn);
            asm volatile("cp.async.commit_group;" ::: "memory");
            asm volatile("cp.async.wait_group 1;" ::: "memory");
        } else {
            asm volatile("cp.async.wait_group 0;" ::: "memory");
        }
        __syncthreads();

        int buf = kc & 1;
#pragma unroll
        for (int k8 = 0; k8 < 2; ++k8) {
            int kb = k8*8;
            float af[4][4], bf[4][2];
#pragma unroll
            for (int mt=0;mt<4;mt++) {
                int rm = wm*64 + mt*16;
                af[mt][0]=As[buf][rm+gq][kb+tig];   af[mt][1]=As[buf][rm+gq+8][kb+tig];
                af[mt][2]=As[buf][rm+gq][kb+tig+4]; af[mt][3]=As[buf][rm+gq+8][kb+tig+4];
            }
#pragma unroll
            for (int nt=0;nt<4;nt++) {
                int rn = wn*32 + nt*8;
                bf[nt][0]=Bs[buf][rn+gq][kb+tig]; bf[nt][1]=Bs[buf][rn+gq][kb+tig+4];
            }
#pragma unroll
            for (int mt=0;mt<4;mt++)
#pragma unroll
                for (int nt=0;nt<4;nt++)
                    mma8(acc[mt][nt], af[mt], bf[nt]);
        }
        __syncthreads();
    }

    float2 lb[4];
#pragma unroll
    for (int nt=0;nt<4;nt++) {
        int v = v0 + wn*32 + nt*8 + tig*2;
        lb[nt] = *(const float2*)(linb + v);
    }
#pragma unroll
    for (int mt=0;mt<4;mt++) {
#pragma unroll
        for (int half=0; half<2; ++half) {
            int ml = wm*64 + mt*16 + gq + half*8;
            int p = m0 + ml;
            if (p < P) {
                int tt = g_pt[p], bb = g_pb[p];
                size_t base = ((size_t)bb*TDEC + tt)*VV + v0 + wn*32 + tig*2;
#pragma unroll
                for (int nt=0;nt<4;nt++) {
                    float2 val;
                    val.x = acc[mt][nt][half*2+0] + lb[nt].x;
                    val.y = acc[mt][nt][half*2+1] + lb[nt].y;
                    *(float2*)(out + base + nt*8) = val;
                }
            }
        }
    }
}

// ------------------------ launch ------------------------
extern "C" void kernel_launch(void* const* d_in, const int* in_sizes, int n_in,
                              void* d_out, int out_size)
{
    const float* img  = (const float*)d_in[0];
    const int*   caps = (const int*)  d_in[1];
    const int*   lens = (const int*)  d_in[2];
    const float* embW = (const float*)d_in[3];
    const float* Wih  = (const float*)d_in[4];
    const float* Whh  = (const float*)d_in[5];
    const float* bih  = (const float*)d_in[6];
    const float* bhh  = (const float*)d_in[7];
    const float* linW = (const float*)d_in[8];
    const float* linb = (const float*)d_in[9];
    float* out = (float*)d_out;

    setup_kernel<<<1, 256>>>(img, caps, lens, out, out_size);
    round_linW<<<(VV*HD/4)/256, 256>>>(linW);
    zerofill_kernel<<<BB*TDEC, 256>>>(out);
    xgate_mma<<<dim3(GG/128, (MAXP+127)/128), 256>>>(embW, Wih, bih, bhh);
    recur_kernel<<<NBLK, 256>>>(Whh);
    classifier_mma<<<dim3(VV/128, (MAXP+127)/128), 256>>>(linb, out);
}

// round 6
// speedup vs baseline: 2.4506x; 1.6508x over previous
#include <cuda_runtime.h>
#include <stdint.h>
#include <math.h>

#define BB   64
#define TT   52
#define TDEC 51
#define HD   512
#define EE   512
#define GG   2048
#define VV   32000
#define PRED_ELEMS (BB*TDEC*VV)
#define MAXP (BB*TDEC)
#define NBLK 128
#define WP   516                       // padded pitch (floats) for smem tiles
#define RECUR_SMEM ((16*WP + 64*WP)*4) // 165120 bytes

// ------------------------ device scratch ------------------------
__device__ int   g_sort_ind[BB];
__device__ int   g_declen[BB];
__device__ int   g_nt[TDEC];
__device__ int   g_pbase[TDEC];
__device__ int   g_pcount;
__device__ int   g_caps[BB*TT];
__device__ int   g_pt[MAXP];
__device__ int   g_pb[MAXP];
__device__ int   g_pcap[MAXP];
__device__ float g_h[BB*HD];
__device__ float g_gates[BB*GG];
__device__ float g_X[(size_t)TDEC*BB*GG];
__device__ float g_Hpk[(size_t)MAXP*HD];          // tf32-rounded h history
__device__ float g_linWr[(size_t)VV*HD];          // tf32-rounded lin_W (64MB)
__device__ unsigned g_bar_count;
__device__ unsigned g_bar_sense;

// ------------------------ helpers ------------------------
__device__ __forceinline__ float to_tf32(float x) {
    float r; asm("cvt.rna.tf32.f32 %0, %1;" : "=f"(r) : "f"(x)); return r;
}
__device__ __forceinline__ void st4_split(float* dh, float* dl, float4 r) {
    float h;
    h=to_tf32(r.x); dh[0]=h; dl[0]=to_tf32(r.x-h);
    h=to_tf32(r.y); dh[1]=h; dl[1]=to_tf32(r.y-h);
    h=to_tf32(r.z); dh[2]=h; dl[2]=to_tf32(r.z-h);
    h=to_tf32(r.w); dh[3]=h; dl[3]=to_tf32(r.w-h);
}
__device__ __forceinline__ void mma8(float* d, const float* a, const float* b) {
    asm volatile("mma.sync.aligned.m16n8k8.row.col.f32.tf32.tf32.f32 "
        "{%0,%1,%2,%3}, {%4,%5,%6,%7}, {%8,%9}, {%0,%1,%2,%3};"
        : "+f"(d[0]), "+f"(d[1]), "+f"(d[2]), "+f"(d[3])
        : "r"(__float_as_uint(a[0])), "r"(__float_as_uint(a[1])),
          "r"(__float_as_uint(a[2])), "r"(__float_as_uint(a[3])),
          "r"(__float_as_uint(b[0])), "r"(__float_as_uint(b[1])));
}
__device__ __forceinline__ void cpasync16(uint32_t saddr, const float* gptr) {
    asm volatile("cp.async.cg.shared.global [%0], [%1], 16;"
                 :: "r"(saddr), "l"(gptr) : "memory");
}
__device__ __forceinline__ unsigned long long pack2(float a, float b) {
    unsigned long long r;
    asm("mov.b64 %0, {%1, %2};" : "=l"(r) : "f"(a), "f"(b));
    return r;
}
__device__ __forceinline__ unsigned long long fma2(unsigned long long a,
                                                   unsigned long long b,
                                                   unsigned long long c) {
    unsigned long long r;
    asm("fma.rn.f32x2 %0, %1, %2, %3;" : "=l"(r) : "l"(a), "l"(b), "l"(c));
    return r;
}
__device__ __forceinline__ float hsum2(unsigned long long v) {
    float a, b;
    asm("mov.b64 {%0, %1}, %2;" : "=f"(a), "=f"(b) : "l"(v));
    return a + b;
}
__device__ __forceinline__ void gridbar(unsigned gen) {
    __syncthreads();
    if (threadIdx.x == 0) {
        unsigned prev;
        asm volatile("atom.release.gpu.global.add.u32 %0, [%1], 1;"
                     : "=r"(prev) : "l"(&g_bar_count) : "memory");
        if (prev == NBLK - 1u) {
            g_bar_count = 0u;
            asm volatile("st.release.gpu.global.u32 [%0], %1;"
                         :: "l"(&g_bar_sense), "r"(gen) : "memory");
        } else {
            unsigned s;
            do {
                asm volatile("ld.acquire.gpu.global.u32 %0, [%1];"
                             : "=r"(s) : "l"(&g_bar_sense) : "memory");
            } while (s != gen);
        }
    }
    __syncthreads();
}

// ------------------------ kernel 1: sort + gathers + pair maps ------------------------
__global__ void setup_kernel(const float* __restrict__ img,
                             const int*   __restrict__ caps_in,
                             const int*   __restrict__ lens,
                             float* __restrict__ out, int out_elems)
{
    __shared__ int s_len[BB];
    int tid = threadIdx.x;
    if (tid < BB) s_len[tid] = lens[tid];
    __syncthreads();

    if (tid == 0) {
        unsigned long long used = 0ull;
        for (int p = 0; p < BB; ++p) {
            int best = -1, bl = -1000000;
            for (int j = 0; j < BB; ++j)
                if (!((used >> j) & 1ull) && s_len[j] > bl) { bl = s_len[j]; best = j; }
            used |= 1ull << best;
            g_sort_ind[p] = best;
            g_declen[p]   = bl - 1;
        }
        g_bar_count = 0u;
        g_bar_sense = 0u;
    }
    __syncthreads();

    if (tid < TDEC) {
        int cnt = 0;
        for (int p = 0; p < BB; ++p) cnt += (g_declen[p] > tid) ? 1 : 0;
        g_nt[tid] = cnt;
    }

    bool wt = (out_elems >= PRED_ELEMS + BB*TT + 2*BB);
    for (int idx = tid; idx < BB*TT; idx += blockDim.x) {
        int p = idx / TT, j = idx - p*TT;
        int c = caps_in[g_sort_ind[p]*TT + j];
        g_caps[idx] = c;
        if (wt) out[PRED_ELEMS + idx] = (float)c;
    }
    for (int idx = tid; idx < BB*HD; idx += blockDim.x) {
        int p = idx >> 9;
        g_h[idx] = img[g_sort_ind[p]*HD + (idx & (HD-1))];
    }
    if (wt && tid < BB) {
        out[PRED_ELEMS + BB*TT + tid]      = (float)g_declen[tid];
        out[PRED_ELEMS + BB*TT + BB + tid] = (float)g_sort_ind[tid];
    }
    __syncthreads();
    if (tid == 0) {
        int pb = 0;
        for (int t = 0; t < TDEC; ++t) { g_pbase[t] = pb; pb += g_nt[t]; }
        g_pcount = pb;
    }
    __syncthreads();
    if (tid < TDEC) {
        int n = g_nt[tid], pb = g_pbase[tid];
        for (int b = 0; b < n; ++b) {
            g_pt[pb+b]   = tid;
            g_pb[pb+b]   = b;
            g_pcap[pb+b] = g_caps[b*TT + tid];
        }
    }
}

// ------------------------ kernel 1b: pre-round linW to tf32 ------------------------
__global__ void round_linW(const float* __restrict__ w)
{
    size_t i = (size_t)blockIdx.x * blockDim.x + threadIdx.x;
    const float4* src = (const float4*)w;
    float4 v = src[i];
    v.x = to_tf32(v.x); v.y = to_tf32(v.y); v.z = to_tf32(v.z); v.w = to_tf32(v.w);
    ((float4*)g_linWr)[i] = v;
}

// ------------------------ kernel 2: zero-fill inactive rows ------------------------
__global__ void zerofill_kernel(float* __restrict__ out)
{
    int bid = blockIdx.x;
    int b = bid / TDEC, t = bid - b*TDEC;
    if (t < g_declen[b]) return;
    float4 z = make_float4(0.f,0.f,0.f,0.f);
    float4* dst = (float4*)(out + ((size_t)b*TDEC + t)*VV);
    for (int i = threadIdx.x; i < VV/4; i += blockDim.x) dst[i] = z;
}

// ------------------------ kernel 3: xgate via tf32x3 mma ------------------------
__global__ void __launch_bounds__(256) xgate_mma(const float* __restrict__ embW,
                                                const float* __restrict__ Wih,
                                                const float* __restrict__ bih,
                                                const float* __restrict__ bhh)
{
    int P  = g_pcount;
    int m0 = blockIdx.y * 128;
    if (m0 >= P) return;
    int j0 = blockIdx.x * 128;

    __shared__ float Ah[128][20], Al[128][20], Bh[128][20], Bl[128][20];

    int tid  = threadIdx.x;
    int lane = tid & 31, wid = tid >> 5;
    int wm = wid & 1, wn = wid >> 1;
    int gq = lane >> 2, tig = lane & 3;

    int lrow = tid >> 2;
    int lkq  = (tid & 3) * 4;
    int p0 = m0 + lrow, p1 = m0 + lrow + 64;
    bool va0 = p0 < P, va1 = p1 < P;
    const float* a0p = va0 ? (embW + (size_t)g_pcap[p0]*EE + lkq) : (embW + lkq);
    const float* a1p = va1 ? (embW + (size_t)g_pcap[p1]*EE + lkq) : (embW + lkq);
    const float* b0p = Wih + (size_t)(j0+lrow)*EE + lkq;
    const float* b1p = Wih + (size_t)(j0+lrow+64)*EE + lkq;

    float acc[4][4][4];
#pragma unroll
    for (int i=0;i<4;i++)
#pragma unroll
        for (int j=0;j<4;j++)
#pragma unroll
            for (int q=0;q<4;q++) acc[i][j][q] = 0.f;

    for (int kc = 0; kc < 32; ++kc) {
        int k0 = kc*16;
        float4 ra0 = va0 ? *(const float4*)(a0p + k0) : make_float4(0,0,0,0);
        float4 ra1 = va1 ? *(const float4*)(a1p + k0) : make_float4(0,0,0,0);
        float4 rb0 = *(const float4*)(b0p + k0);
        float4 rb1 = *(const float4*)(b1p + k0);
        __syncthreads();
        st4_split(&Ah[lrow][lkq],    &Al[lrow][lkq],    ra0);
        st4_split(&Ah[lrow+64][lkq], &Al[lrow+64][lkq], ra1);
        st4_split(&Bh[lrow][lkq],    &Bl[lrow][lkq],    rb0);
        st4_split(&Bh[lrow+64][lkq], &Bl[lrow+64][lkq], rb1);
        __syncthreads();
#pragma unroll
        for (int k8 = 0; k8 < 2; ++k8) {
            int kb = k8*8;
            float ah[4][4], al[4][4], bh[4][2], bl[4][2];
#pragma unroll
            for (int mt=0;mt<4;mt++) {
                int rm = wm*64 + mt*16;
                ah[mt][0]=Ah[rm+gq][kb+tig];   ah[mt][1]=Ah[rm+gq+8][kb+tig];
                ah[mt][2]=Ah[rm+gq][kb+tig+4]; ah[mt][3]=Ah[rm+gq+8][kb+tig+4];
                al[mt][0]=Al[rm+gq][kb+tig];   al[mt][1]=Al[rm+gq+8][kb+tig];
                al[mt][2]=Al[rm+gq][kb+tig+4]; al[mt][3]=Al[rm+gq+8][kb+tig+4];
            }
#pragma unroll
            for (int nt=0;nt<4;nt++) {
                int rn = wn*32 + nt*8;
                bh[nt][0]=Bh[rn+gq][kb+tig]; bh[nt][1]=Bh[rn+gq][kb+tig+4];
                bl[nt][0]=Bl[rn+gq][kb+tig]; bl[nt][1]=Bl[rn+gq][kb+tig+4];
            }
#pragma unroll
            for (int mt=0;mt<4;mt++)
#pragma unroll
                for (int nt=0;nt<4;nt++) {
                    mma8(acc[mt][nt], ah[mt], bh[nt]);
                    mma8(acc[mt][nt], ah[mt], bl[nt]);
                    mma8(acc[mt][nt], al[mt], bh[nt]);
                }
        }
    }

    float2 lb[4];
#pragma unroll
    for (int nt=0;nt<4;nt++) {
        int v = j0 + wn*32 + nt*8 + tig*2;
        float2 bi = *(const float2*)(bih + v);
        float2 bh2 = *(const float2*)(bhh + v);
        lb[nt].x = bi.x + bh2.x; lb[nt].y = bi.y + bh2.y;
    }
#pragma unroll
    for (int mt=0;mt<4;mt++) {
#pragma unroll
        for (int half=0; half<2; ++half) {
            int ml = wm*64 + mt*16 + gq + half*8;
            int p = m0 + ml;
            if (p < P) {
                int tt = g_pt[p], bb = g_pb[p];
                size_t base = (size_t)tt*BB*GG + (size_t)bb*GG + j0 + wn*32 + tig*2;
#pragma unroll
                for (int nt=0;nt<4;nt++) {
                    float2 val;
                    val.x = acc[mt][nt][half*2+0] + lb[nt].x;
                    val.y = acc[mt][nt][half*2+1] + lb[nt].y;
                    *(float2*)(g_X + base + nt*8) = val;
                }
            }
        }
    }
}

// ------------------------ kernel 4: persistent LSTM recurrence (smem-staged, f32x2) ------------------------
__global__ void __launch_bounds__(256) recur_kernel(const float* __restrict__ Whh)
{
    extern __shared__ float sm[];
    float* sWT = sm;             // [16][WP] : W^T slice, row = local col, pitch WP
    float* sH  = sm + 16*WP;     // [64][WP] : h staged per step

    int tid = threadIdx.x;
    int blk = blockIdx.x;
    int c0 = blk * 16;

    // load W slice once (transposed: sWT[c][k])
    for (int idx = tid; idx < 16*HD; idx += 256) {
        int c = idx >> 9, k = idx & (HD-1);
        sWT[c*WP + k] = Whh[(size_t)(c0+c)*HD + k];
    }

    int rgrp = tid >> 4;          // 0..15 -> rows rgrp*4..+3
    int cc   = tid & 15;
    int col  = c0 + cc;
    int r0   = rgrp*4;
    int eb   = blk*256 + tid;
    int b_u  = eb >> 9, k_u = eb & (HD-1);

    const float* wbase = sWT + cc*WP;
    const float* h0p = sH + (size_t)(r0+0)*WP;
    const float* h1p = sH + (size_t)(r0+1)*WP;
    const float* h2p = sH + (size_t)(r0+2)*WP;
    const float* h3p = sH + (size_t)(r0+3)*WP;

    // cp.async staging addresses: each thread stages rows (tid>>7)+2j at quad kq=tid&127
    int srow0 = tid >> 7;            // 0..1
    int skq   = tid & 127;
    uint32_t sdst0 = (uint32_t)__cvta_generic_to_shared(sH + (size_t)srow0*WP + skq*4);
    const float* sg0 = g_h + (size_t)srow0*HD + skq*4;
    const uint32_t SROWB = 2u*WP*4u;     // smem bytes per 2 rows

    float creg = 0.f;
    unsigned gen = 0;
    __syncthreads();

    for (int t = 0; t < TDEC; ++t) {
        int n = g_nt[t];

        // prefetch update-phase x-gate inputs early (hide DRAM latency behind gates)
        const float* gx = g_X + (size_t)t*BB*GG + (size_t)b_u*GG + k_u;
        float x0=0.f, x1=0.f, x2=0.f, x3=0.f;
        if (b_u < n) {
            x0 = __ldcg(gx); x1 = __ldcg(gx+HD); x2 = __ldcg(gx+2*HD); x3 = __ldcg(gx+3*HD);
        }

        // stage h into smem
#pragma unroll
        for (int j = 0; j < 32; ++j) {
            cpasync16(sdst0 + (uint32_t)j*SROWB, sg0 + (size_t)j*2*HD);
        }
        asm volatile("cp.async.commit_group;" ::: "memory");
        asm volatile("cp.async.wait_group 0;" ::: "memory");
        __syncthreads();

        if (r0 < n) {
            unsigned long long a00=0ull,a01=0ull,a10=0ull,a11=0ull,
                               a20=0ull,a21=0ull,a30=0ull,a31=0ull;
#pragma unroll 4
            for (int kq = 0; kq < HD/4; ++kq) {
                float4 wv = *(const float4*)(wbase + 4*kq);
                unsigned long long wxy = pack2(wv.x, wv.y);
                unsigned long long wzw = pack2(wv.z, wv.w);
                float4 v0 = *(const float4*)(h0p + 4*kq);
                float4 v1 = *(const float4*)(h1p + 4*kq);
                float4 v2 = *(const float4*)(h2p + 4*kq);
                float4 v3 = *(const float4*)(h3p + 4*kq);
                a00 = fma2(pack2(v0.x,v0.y), wxy, a00);
                a01 = fma2(pack2(v0.z,v0.w), wzw, a01);
                a10 = fma2(pack2(v1.x,v1.y), wxy, a10);
                a11 = fma2(pack2(v1.z,v1.w), wzw, a11);
                a20 = fma2(pack2(v2.x,v2.y), wxy, a20);
                a21 = fma2(pack2(v2.z,v2.w), wzw, a21);
                a30 = fma2(pack2(v3.x,v3.y), wxy, a30);
                a31 = fma2(pack2(v3.z,v3.w), wzw, a31);
            }
            if (r0+0 < n) g_gates[(size_t)(r0+0)*GG + col] = hsum2(a00) + hsum2(a01);
            if (r0+1 < n) g_gates[(size_t)(r0+1)*GG + col] = hsum2(a10) + hsum2(a11);
            if (r0+2 < n) g_gates[(size_t)(r0+2)*GG + col] = hsum2(a20) + hsum2(a21);
            if (r0+3 < n) g_gates[(size_t)(r0+3)*GG + col] = hsum2(a30) + hsum2(a31);
        }
        gen++; gridbar(gen);

        if (b_u < n) {
            const float* gr = g_gates + (size_t)b_u*GG + k_u;
            float zi = __ldcg(gr)        + x0;
            float zf = __ldcg(gr +   HD) + x1;
            float zg = __ldcg(gr + 2*HD) + x2;
            float zo = __ldcg(gr + 3*HD) + x3;
            float ii = 1.f/(1.f+expf(-zi));
            float ff = 1.f/(1.f+expf(-zf));
            float gv = tanhf(zg);
            float oo = 1.f/(1.f+expf(-zo));
            creg = ff*creg + ii*gv;
            float hn = oo * tanhf(creg);
            g_h[(size_t)b_u*HD + k_u] = hn;
            g_Hpk[(size_t)(g_pbase[t] + b_u)*HD + k_u] = to_tf32(hn);
        }
        gen++; gridbar(gen);
    }
}

// ------------------------ kernel 5: classifier, cp.async double-buffered tf32 mma ------------------------
__global__ void __launch_bounds__(256,2) classifier_mma(const float* __restrict__ linb,
                                                        float* __restrict__ out)
{
    int P  = g_pcount;
    int m0 = blockIdx.y * 128;
    if (m0 >= P) return;
    int v0 = blockIdx.x * 128;

    __shared__ float As[2][128][20];
    __shared__ float Bs[2][128][20];

    int tid  = threadIdx.x;
    int lane = tid & 31, wid = tid >> 5;
    int wm = wid & 1, wn = wid >> 1;
    int gq = lane >> 2, tig = lane & 3;

    int lrow = tid >> 2;
    int lkq  = (tid & 3) * 4;
    int p0 = m0 + lrow, p1 = m0 + lrow + 64;
    const float* a0p = g_Hpk + (size_t)(p0 < P ? p0 : 0)*HD + lkq;
    const float* a1p = g_Hpk + (size_t)(p1 < P ? p1 : 0)*HD + lkq;
    const float* b0p = g_linWr + (size_t)(v0+lrow)*HD + lkq;
    const float* b1p = g_linWr + (size_t)(v0+lrow+64)*HD + lkq;

    uint32_t sa0 = (uint32_t)__cvta_generic_to_shared(&As[0][lrow][lkq]);
    uint32_t sa1 = (uint32_t)__cvta_generic_to_shared(&As[0][lrow+64][lkq]);
    uint32_t sb0 = (uint32_t)__cvta_generic_to_shared(&Bs[0][lrow][lkq]);
    uint32_t sb1 = (uint32_t)__cvta_generic_to_shared(&Bs[0][lrow+64][lkq]);
    const uint32_t STG = 128*20*4;   // bytes per stage

    float acc[4][4][4];
#pragma unroll
    for (int i=0;i<4;i++)
#pragma unroll
        for (int j=0;j<4;j++)
#pragma unroll
            for (int q=0;q<4;q++) acc[i][j][q] = 0.f;

    cpasync16(sa0, a0p);
    cpasync16(sa1, a1p);
    cpasync16(sb0, b0p);
    cpasync16(sb1, b1p);
    asm volatile("cp.async.commit_group;" ::: "memory");

    for (int kc = 0; kc < 32; ++kc) {
        if (kc < 31) {
            uint32_t off = ((kc+1)&1) * STG;
            int kn = (kc+1)*16;
            cpasync16(sa0 + off, a0p + kn);
            cpasync16(sa1 + off, a1p + kn);
            cpasync16(sb0 + off, b0p + kn);
            cpasync16(sb1 + off, b1p + kn);
            asm volatile("cp.async.commit_group;" ::: "memory");
            asm volatile("cp.async.wait_group 1;" ::: "memory");
        } else {
            asm volatile("cp.async.wait_group 0;" ::: "memory");
        }
        __syncthreads();

        int buf = kc & 1;
#pragma unroll
        for (int k8 = 0; k8 < 2; ++k8) {
            int kb = k8*8;
            float af[4][4], bf[4][2];
#pragma unroll
            for (int mt=0;mt<4;mt++) {
                int rm = wm*64 + mt*16;
                af[mt][0]=As[buf][rm+gq][kb+tig];   af[mt][1]=As[buf][rm+gq+8][kb+tig];
                af[mt][2]=As[buf][rm+gq][kb+tig+4]; af[mt][3]=As[buf][rm+gq+8][kb+tig+4];
            }
#pragma unroll
            for (int nt=0;nt<4;nt++) {
                int rn = wn*32 + nt*8;
                bf[nt][0]=Bs[buf][rn+gq][kb+tig]; bf[nt][1]=Bs[buf][rn+gq][kb+tig+4];
            }
#pragma unroll
            for (int mt=0;mt<4;mt++)
#pragma unroll
                for (int nt=0;nt<4;nt++)
                    mma8(acc[mt][nt], af[mt], bf[nt]);
        }
        __syncthreads();
    }

    float2 lb[4];
#pragma unroll
    for (int nt=0;nt<4;nt++) {
        int v = v0 + wn*32 + nt*8 + tig*2;
        lb[nt] = *(const float2*)(linb + v);
    }
#pragma unroll
    for (int mt=0;mt<4;mt++) {
#pragma unroll
        for (int half=0; half<2; ++half) {
            int ml = wm*64 + mt*16 + gq + half*8;
            int p = m0 + ml;
            if (p < P) {
                int tt = g_pt[p], bb = g_pb[p];
                size_t base = ((size_t)bb*TDEC + tt)*VV + v0 + wn*32 + tig*2;
#pragma unroll
                for (int nt=0;nt<4;nt++) {
                    float2 val;
                    val.x = acc[mt][nt][half*2+0] + lb[nt].x;
                    val.y = acc[mt][nt][half*2+1] + lb[nt].y;
                    *(float2*)(out + base + nt*8) = val;
                }
            }
        }
    }
}

// ------------------------ launch ------------------------
extern "C" void kernel_launch(void* const* d_in, const int* in_sizes, int n_in,
                              void* d_out, int out_size)
{
    const float* img  = (const float*)d_in[0];
    const int*   caps = (const int*)  d_in[1];
    const int*   lens = (const int*)  d_in[2];
    const float* embW = (const float*)d_in[3];
    const float* Wih  = (const float*)d_in[4];
    const float* Whh  = (const float*)d_in[5];
    const float* bih  = (const float*)d_in[6];
    const float* bhh  = (const float*)d_in[7];
    const float* linW = (const float*)d_in[8];
    const float* linb = (const float*)d_in[9];
    float* out = (float*)d_out;

    static int smem_set = 0;
    if (!smem_set) {
        cudaFuncSetAttribute(recur_kernel,
                             cudaFuncAttributeMaxDynamicSharedMemorySize, RECUR_SMEM);
        smem_set = 1;
    }

    setup_kernel<<<1, 256>>>(img, caps, lens, out, out_size);
    round_linW<<<(VV*HD/4)/256, 256>>>(linW);
    zerofill_kernel<<<BB*TDEC, 256>>>(out);
    xgate_mma<<<dim3(GG/128, (MAXP+127)/128), 256>>>(embW, Wih, bih, bhh);
    recur_kernel<<<NBLK, 256, RECUR_SMEM>>>(Whh);
    classifier_mma<<<dim3(VV/128, (MAXP+127)/128), 256>>>(linb, out);
}